// round 1
// baseline (speedup 1.0000x reference)
#include <cuda_runtime.h>

#define B_  4
#define H_  16
#define T_  2048
#define DK_ 64
#define DM_ 1024
#define M_  (B_*T_)     // 8192

// Scratch (device globals — no allocations allowed)
__device__ float g_Q[B_*H_*T_*DK_];     // [b][h][t][d]
__device__ float g_K[B_*H_*T_*DK_];
__device__ float g_V[B_*H_*T_*DK_];
__device__ float g_att[B_*T_*DM_];      // [b][t][h*64+d]

// ---------------------------------------------------------------------------
// GEMM: C = A @ W^T + bias
//   A: [M, 1024] row-major, W: [1024, 1024] row-major (rows = output features)
//   mode 0: write split-head layout  C[((b*16+h)*2048 + t)*64 + d]
//   mode 1: plain row-major          C[m*1024 + n]
// 128x128 tile, BK=16, 256 threads, 8x8 per thread.
// ---------------------------------------------------------------------------
__global__ __launch_bounds__(256) void gemm_kernel(
    const float* __restrict__ A, const float* __restrict__ W,
    const float* __restrict__ bias, float* __restrict__ C, int mode)
{
    __shared__ float As[16][128];
    __shared__ float Bs[16][128];

    const int tid = threadIdx.x;
    const int m0  = blockIdx.y * 128;
    const int n0  = blockIdx.x * 128;
    const int ty  = tid >> 4;          // 0..15
    const int tx  = tid & 15;          // 0..15

    float acc[8][8];
    #pragma unroll
    for (int i = 0; i < 8; i++)
        #pragma unroll
        for (int j = 0; j < 8; j++) acc[i][j] = 0.f;

    for (int k0 = 0; k0 < 1024; k0 += 16) {
        // Load 128x16 tiles of A and W (transposed into smem), float4.
        #pragma unroll
        for (int i = 0; i < 2; i++) {
            int f  = i * 256 + tid;        // 0..511
            int r  = f >> 2;               // row within tile 0..127
            int cv = (f & 3) << 2;         // k-offset 0,4,8,12
            float4 va = *(const float4*)(A + (size_t)(m0 + r) * 1024 + k0 + cv);
            As[cv+0][r] = va.x; As[cv+1][r] = va.y;
            As[cv+2][r] = va.z; As[cv+3][r] = va.w;
            float4 vb = *(const float4*)(W + (size_t)(n0 + r) * 1024 + k0 + cv);
            Bs[cv+0][r] = vb.x; Bs[cv+1][r] = vb.y;
            Bs[cv+2][r] = vb.z; Bs[cv+3][r] = vb.w;
        }
        __syncthreads();

        #pragma unroll
        for (int k = 0; k < 16; k++) {
            float ra[8], rb[8];
            #pragma unroll
            for (int j = 0; j < 8; j++) ra[j] = As[k][ty*8 + j];
            #pragma unroll
            for (int j = 0; j < 8; j++) rb[j] = Bs[k][tx*8 + j];
            #pragma unroll
            for (int i = 0; i < 8; i++)
                #pragma unroll
                for (int j = 0; j < 8; j++)
                    acc[i][j] += ra[i] * rb[j];
        }
        __syncthreads();
    }

    // Epilogue
    #pragma unroll
    for (int i = 0; i < 8; i++) {
        int m = m0 + ty*8 + i;
        int b = m >> 11;          // /2048
        int t = m & 2047;
        #pragma unroll
        for (int j = 0; j < 8; j++) {
            int n = n0 + tx*8 + j;
            float v = acc[i][j] + bias[n];
            if (mode == 0) {
                int h = n >> 6, d = n & 63;
                C[(((size_t)(b*16 + h))*2048 + t)*64 + d] = v;
            } else {
                C[(size_t)m * 1024 + n] = v;
            }
        }
    }
}

// ---------------------------------------------------------------------------
// Flash attention (fp32, causal).
// Grid: (T/64, B*H). Block: 256 threads = 8 warps; warp w owns Q rows w*8..w*8+7.
// Lane owns S/O columns {lane, lane+32}. Online softmax, P staged via smem.
// ---------------------------------------------------------------------------
#define KV_PAD 68   // 68 floats/row = 272B: 16B-aligned rows, conflict-free (4*lane+d)%32

__global__ __launch_bounds__(256) void attn_kernel(
    const float* __restrict__ Q, const float* __restrict__ K,
    const float* __restrict__ V, float* __restrict__ att)
{
    extern __shared__ float sm[];
    float* Qs = sm;                    // [64][64]
    float* Ks = sm + 64*64;            // [64][KV_PAD]
    float* Vs = Ks + 64*KV_PAD;        // [64][KV_PAD]
    float* Ps = Vs + 64*KV_PAD;        // [64][64]

    const int tid  = threadIdx.x;
    const int w    = tid >> 5;
    const int lane = tid & 31;
    const int qi   = blockIdx.x;
    const int bh   = blockIdx.y;
    const size_t base = (size_t)bh * T_ * DK_;

    // Load Q tile (contiguous 64x64 block), pre-scale by 1/sqrt(64)
    {
        const float4* src = (const float4*)(Q + base + (size_t)qi * 64 * 64);
        #pragma unroll
        for (int i = 0; i < 4; i++) {
            int f = i*256 + tid;           // 0..1023 float4s
            float4 v = src[f];
            int r = f >> 4, c = (f & 15) << 2;
            float* qp = Qs + r*64 + c;
            qp[0] = v.x * 0.125f; qp[1] = v.y * 0.125f;
            qp[2] = v.z * 0.125f; qp[3] = v.w * 0.125f;
        }
    }

    float m_i[8], l_i[8], o0[8], o1[8];
    #pragma unroll
    for (int r = 0; r < 8; r++) { m_i[r] = -1e30f; l_i[r] = 0.f; o0[r] = 0.f; o1[r] = 0.f; }

    __syncthreads();

    for (int kt = 0; kt <= qi; kt++) {
        // Load K,V 64x64 tiles (contiguous)
        const float4* ksrc = (const float4*)(K + base + (size_t)kt * 64 * 64);
        const float4* vsrc = (const float4*)(V + base + (size_t)kt * 64 * 64);
        #pragma unroll
        for (int i = 0; i < 4; i++) {
            int f = i*256 + tid;
            int r = f >> 4, c = (f & 15) << 2;
            float4 kv = ksrc[f];
            float* kp = Ks + r*KV_PAD + c;
            kp[0]=kv.x; kp[1]=kv.y; kp[2]=kv.z; kp[3]=kv.w;
            float4 vv = vsrc[f];
            float* vp = Vs + r*KV_PAD + c;
            vp[0]=vv.x; vp[1]=vv.y; vp[2]=vv.z; vp[3]=vv.w;
        }
        __syncthreads();

        const bool diag = (kt == qi);

        // S = Q K^T, online softmax, stage P
        #pragma unroll 1
        for (int r = 0; r < 8; r++) {
            const int i = w*8 + r;
            float s0 = 0.f, s1 = 0.f;
            const float4* qrow = (const float4*)(Qs + i*64);
            const float4* k0p  = (const float4*)(Ks + lane*KV_PAD);
            const float4* k1p  = (const float4*)(Ks + (lane+32)*KV_PAD);
            #pragma unroll
            for (int d4 = 0; d4 < 16; d4++) {
                float4 q = qrow[d4];
                float4 a = k0p[d4];
                float4 b = k1p[d4];
                s0 += q.x*a.x + q.y*a.y + q.z*a.z + q.w*a.w;
                s1 += q.x*b.x + q.y*b.y + q.z*b.z + q.w*b.w;
            }
            if (diag) {
                if (lane      > i) s0 = -1e30f;
                if (lane + 32 > i) s1 = -1e30f;
            }
            float mloc = fmaxf(s0, s1);
            #pragma unroll
            for (int off = 16; off > 0; off >>= 1)
                mloc = fmaxf(mloc, __shfl_xor_sync(0xffffffffu, mloc, off));
            float mnew = fmaxf(m_i[r], mloc);
            float p0 = __expf(s0 - mnew);
            float p1 = __expf(s1 - mnew);
            float rs = p0 + p1;
            #pragma unroll
            for (int off = 16; off > 0; off >>= 1)
                rs += __shfl_xor_sync(0xffffffffu, rs, off);
            float corr = __expf(m_i[r] - mnew);
            l_i[r] = l_i[r]*corr + rs;
            o0[r] *= corr;
            o1[r] *= corr;
            m_i[r] = mnew;
            Ps[i*64 + lane]      = p0;
            Ps[i*64 + lane + 32] = p1;
        }
        __syncwarp();

        // O += P V  (chunked over j for float4 P reads)
        #pragma unroll 1
        for (int jc = 0; jc < 64; jc += 4) {
            float v0[4], v1[4];
            #pragma unroll
            for (int jj = 0; jj < 4; jj++) {
                v0[jj] = Vs[(jc+jj)*KV_PAD + lane];
                v1[jj] = Vs[(jc+jj)*KV_PAD + lane + 32];
            }
            #pragma unroll
            for (int r = 0; r < 8; r++) {
                const int i = w*8 + r;
                float4 p = *(const float4*)(Ps + i*64 + jc);
                o0[r] += p.x*v0[0] + p.y*v0[1] + p.z*v0[2] + p.w*v0[3];
                o1[r] += p.x*v1[0] + p.y*v1[1] + p.z*v1[2] + p.w*v1[3];
            }
        }
        __syncthreads();
    }

    // Normalize and write to [B, T, D_MODEL] layout for the O-projection
    const int b = bh >> 4, h = bh & 15;
    #pragma unroll
    for (int r = 0; r < 8; r++) {
        int i = w*8 + r;
        int t = qi*64 + i;
        float inv = 1.0f / l_i[r];
        float* dst = att + ((size_t)(b*T_ + t)) * DM_ + h*DK_;
        dst[lane]      = o0[r] * inv;
        dst[lane + 32] = o1[r] * inv;
    }
}

// ---------------------------------------------------------------------------
extern "C" void kernel_launch(void* const* d_in, const int* in_sizes, int n_in,
                              void* d_out, int out_size)
{
    const float* x   = (const float*)d_in[0];
    // d_in[1] = mask (int32, causal tril) — causality is computed analytically
    const float* Wq  = (const float*)d_in[2];
    const float* Wqb = (const float*)d_in[3];
    const float* Wk  = (const float*)d_in[4];
    const float* Wkb = (const float*)d_in[5];
    const float* Wv  = (const float*)d_in[6];
    const float* Wvb = (const float*)d_in[7];
    const float* Wo  = (const float*)d_in[8];
    const float* Wob = (const float*)d_in[9];
    float* out = (float*)d_out;

    float *Qp, *Kp, *Vp, *Ap;
    cudaGetSymbolAddress((void**)&Qp, g_Q);
    cudaGetSymbolAddress((void**)&Kp, g_K);
    cudaGetSymbolAddress((void**)&Vp, g_V);
    cudaGetSymbolAddress((void**)&Ap, g_att);

    const int attn_smem = (64*64 + 2*64*KV_PAD + 64*64) * (int)sizeof(float); // 67584 B
    cudaFuncSetAttribute(attn_kernel, cudaFuncAttributeMaxDynamicSharedMemorySize, attn_smem);

    dim3 ggrid(DM_/128, M_/128);   // (8, 64)
    gemm_kernel<<<ggrid, 256>>>(x, Wq, Wqb, Qp, 0);
    gemm_kernel<<<ggrid, 256>>>(x, Wk, Wkb, Kp, 0);
    gemm_kernel<<<ggrid, 256>>>(x, Wv, Wvb, Vp, 0);

    attn_kernel<<<dim3(T_/64, B_*H_), 256, attn_smem>>>(Qp, Kp, Vp, Ap);

    gemm_kernel<<<ggrid, 256>>>(Ap, Wo, Wob, out, 1);
}

// round 5
// speedup vs baseline: 1.5482x; 1.5482x over previous
#include <cuda_runtime.h>
#include <cuda_bf16.h>
#include <cstdint>

#define B_  4
#define H_  16
#define T_  2048
#define DK_ 64
#define DM_ 1024
#define M_  (B_*T_)     // 8192

// ---------------- scratch (device globals; no allocations allowed) ----------
__device__ __nv_bfloat16 g_xhi[M_*DM_];
__device__ __nv_bfloat16 g_xlo[M_*DM_];
__device__ __nv_bfloat16 g_whi[4*DM_*DM_];
__device__ __nv_bfloat16 g_wlo[4*DM_*DM_];
__device__ __nv_bfloat16 g_ahi[M_*DM_];
__device__ __nv_bfloat16 g_alo[M_*DM_];
__device__ float g_Q[M_*DM_];
__device__ float g_K[M_*DM_];
__device__ float g_V[M_*DM_];
__device__ float g_att[M_*DM_];

// ---------------- portable PTX helpers (family-safe: no tcgen05) -------------
__device__ __forceinline__ uint32_t smem_u32(const void* p) {
    uint32_t a;
    asm("{ .reg .u64 t; cvta.to.shared.u64 t, %1; cvt.u32.u64 %0, t; }" : "=r"(a) : "l"(p));
    return a;
}
__device__ __forceinline__ void cp_async16(uint32_t saddr, const void* gaddr) {
    asm volatile("cp.async.cg.shared.global [%0], [%1], 16;" :: "r"(saddr), "l"(gaddr));
}
#define CP_COMMIT() asm volatile("cp.async.commit_group;" ::: "memory")
#define CP_WAIT(n)  asm volatile("cp.async.wait_group %0;" :: "n"(n) : "memory")

__device__ __forceinline__ void ldsm_x4(uint32_t addr, uint32_t& r0, uint32_t& r1,
                                        uint32_t& r2, uint32_t& r3) {
    asm volatile("ldmatrix.sync.aligned.m8n8.x4.shared.b16 {%0,%1,%2,%3}, [%4];"
                 : "=r"(r0), "=r"(r1), "=r"(r2), "=r"(r3) : "r"(addr));
}
__device__ __forceinline__ void mma_bf16(float* c, const uint32_t* a, const uint32_t* b) {
    asm volatile(
        "mma.sync.aligned.m16n8k16.row.col.f32.bf16.bf16.f32 "
        "{%0,%1,%2,%3}, {%4,%5,%6,%7}, {%8,%9}, {%0,%1,%2,%3};"
        : "+f"(c[0]), "+f"(c[1]), "+f"(c[2]), "+f"(c[3])
        : "r"(a[0]), "r"(a[1]), "r"(a[2]), "r"(a[3]), "r"(b[0]), "r"(b[1]));
}

// ---------------- fp32 -> bf16 hi/lo split -----------------------------------
__global__ __launch_bounds__(256) void split_bf16_kernel(
    const float* __restrict__ x, __nv_bfloat16* __restrict__ hi,
    __nv_bfloat16* __restrict__ lo, int n4)
{
    int i = blockIdx.x * blockDim.x + threadIdx.x;
    if (i >= n4) return;
    float4 v = ((const float4*)x)[i];
    float f[4] = {v.x, v.y, v.z, v.w};
    union { __nv_bfloat16 b[4]; uint2 u; } Hh, Ll;
    #pragma unroll
    for (int k = 0; k < 4; k++) {
        Hh.b[k] = __float2bfloat16(f[k]);
        Ll.b[k] = __float2bfloat16(f[k] - __bfloat162float(Hh.b[k]));
    }
    ((uint2*)hi)[i] = Hh.u;
    ((uint2*)lo)[i] = Ll.u;
}

// ---------------- mma.sync split-bf16 GEMM: C = A @ W^T + bias ---------------
// A[M,1024] (hi/lo), W[1024,1024] (hi/lo) row-major bf16.
// CTA 128x128, BK=32, cp.async double buffer. 8 warps: 4(m) x 2(n), 32x64/warp.
// smem tile: [128][PITCH=40] bf16 (80B rows -> conflict-free ldmatrix).
#define PITCH 40
#define TILE_BYTES (128 * PITCH * 2)      // 10240
#define STAGE_BYTES (4 * TILE_BYTES)      // 40960

__device__ __forceinline__ void issue_stage(uint32_t sb, int stage,
    const __nv_bfloat16* __restrict__ Ahi, const __nv_bfloat16* __restrict__ Alo,
    const __nv_bfloat16* __restrict__ Whi, const __nv_bfloat16* __restrict__ Wlo,
    int m0, int n0, int k0, int tid)
{
    const uint32_t base = sb + stage * STAGE_BYTES;
    const __nv_bfloat16* srcs[4] = {Ahi, Alo, Whi, Wlo};
    const int r0s[4] = {m0, m0, n0, n0};
    #pragma unroll
    for (int t = 0; t < 4; t++) {
        #pragma unroll
        for (int it = 0; it < 2; it++) {
            int idx = it * 256 + tid;          // 0..511
            int r = idx >> 2, c4 = idx & 3;    // 4 x 16B chunks per 64B row
            cp_async16(base + t * TILE_BYTES + r * (PITCH * 2) + c4 * 16,
                       srcs[t] + (size_t)(r0s[t] + r) * 1024 + k0 + c4 * 8);
        }
    }
}

__global__ __launch_bounds__(256) void gemm_tc_kernel(
    const __nv_bfloat16* __restrict__ Ahi, const __nv_bfloat16* __restrict__ Alo,
    const __nv_bfloat16* __restrict__ Whi, const __nv_bfloat16* __restrict__ Wlo,
    const float* __restrict__ bias, float* __restrict__ C, int mode)
{
    extern __shared__ char smem[];
    const uint32_t sb = smem_u32(smem);
    const int tid = threadIdx.x;
    const int wid = tid >> 5, lane = tid & 31;
    const int m0 = blockIdx.y * 128, n0 = blockIdx.x * 128;
    const int wm = (wid & 3) * 32;       // warp m-offset in tile
    const int wn = (wid >> 2) * 64;      // warp n-offset in tile
    const int rl = lane & 7, q = lane >> 3;

    float acc[2][8][4];
    #pragma unroll
    for (int mt = 0; mt < 2; mt++)
        #pragma unroll
        for (int nt = 0; nt < 8; nt++)
            #pragma unroll
            for (int e = 0; e < 4; e++) acc[mt][nt][e] = 0.f;

    issue_stage(sb, 0, Ahi, Alo, Whi, Wlo, m0, n0, 0, tid);
    CP_COMMIT();

    // Per-lane ldmatrix base offsets (within a tile), k-part added per step.
    // A (x4, m16k16): row = mrow + rl + (q&1)*8, colofs = (q>>1)*8
    // B (x4, 2 ntiles k16): row = nrow + rl + (q>>1)*8, colofs = (q&1)*8
    const uint32_t a_row = rl + (q & 1) * 8;
    const uint32_t a_cofs = (q >> 1) * 8;
    const uint32_t b_row = rl + (q >> 1) * 8;
    const uint32_t b_cofs = (q & 1) * 8;

    for (int s = 0; s < 32; s++) {
        if (s < 31) {
            issue_stage(sb, (s + 1) & 1, Ahi, Alo, Whi, Wlo, m0, n0, (s + 1) * 32, tid);
            CP_COMMIT();
            CP_WAIT(1);
        } else {
            CP_WAIT(0);
        }
        __syncthreads();

        const uint32_t st = sb + (s & 1) * STAGE_BYTES;
        #pragma unroll
        for (int k16 = 0; k16 < 32; k16 += 16) {
            uint32_t ah[2][4], al[2][4];
            #pragma unroll
            for (int mt = 0; mt < 2; mt++) {
                uint32_t ro = (wm + mt * 16 + a_row) * (PITCH * 2) + (k16 + a_cofs) * 2;
                ldsm_x4(st + 0 * TILE_BYTES + ro, ah[mt][0], ah[mt][1], ah[mt][2], ah[mt][3]);
                ldsm_x4(st + 1 * TILE_BYTES + ro, al[mt][0], al[mt][1], al[mt][2], al[mt][3]);
            }
            uint32_t bh[8][2], bl[8][2];
            #pragma unroll
            for (int np = 0; np < 4; np++) {     // pairs of n-tiles
                uint32_t ro = (wn + np * 16 + b_row) * (PITCH * 2) + (k16 + b_cofs) * 2;
                ldsm_x4(st + 2 * TILE_BYTES + ro,
                        bh[np*2][0], bh[np*2][1], bh[np*2+1][0], bh[np*2+1][1]);
                ldsm_x4(st + 3 * TILE_BYTES + ro,
                        bl[np*2][0], bl[np*2][1], bl[np*2+1][0], bl[np*2+1][1]);
            }
            #pragma unroll
            for (int mt = 0; mt < 2; mt++)
                #pragma unroll
                for (int nt = 0; nt < 8; nt++) {
                    mma_bf16(acc[mt][nt], ah[mt], bh[nt]);
                    mma_bf16(acc[mt][nt], ah[mt], bl[nt]);
                    mma_bf16(acc[mt][nt], al[mt], bh[nt]);
                }
        }
        __syncthreads();
    }

    // Epilogue
    const int g = lane >> 2, tq = lane & 3;
    #pragma unroll
    for (int mt = 0; mt < 2; mt++) {
        #pragma unroll
        for (int half = 0; half < 2; half++) {
            int m = m0 + wm + mt * 16 + g + half * 8;
            int b = m >> 11, t = m & 2047;
            #pragma unroll
            for (int nt = 0; nt < 8; nt++) {
                int n = n0 + wn + nt * 8 + 2 * tq;
                float2 v;
                v.x = acc[mt][nt][half * 2 + 0] + __ldg(bias + n);
                v.y = acc[mt][nt][half * 2 + 1] + __ldg(bias + n + 1);
                if (mode == 0) {
                    int h = n >> 6, d = n & 63;
                    *(float2*)(C + (((size_t)(b * 16 + h)) * 2048 + t) * 64 + d) = v;
                } else {
                    *(float2*)(C + (size_t)m * 1024 + n) = v;
                }
            }
        }
    }
}

// ---------------- Flash attention (fp32, causal) ----------------------------
#define KV_PAD 68

__global__ __launch_bounds__(256, 2) void attn_kernel(
    const float* __restrict__ Q, const float* __restrict__ K,
    const float* __restrict__ V, float* __restrict__ att)
{
    extern __shared__ float sm[];
    float* Qs = sm;                    // [64][64]
    float* Ks = sm + 64 * 64;          // [64][KV_PAD]
    float* Vs = Ks + 64 * KV_PAD;      // [64][KV_PAD]
    float* Ps = Vs + 64 * KV_PAD;      // [64][64]

    const int tid  = threadIdx.x;
    const int w    = tid >> 5;
    const int lane = tid & 31;
    const int qi   = blockIdx.x;
    const int bh   = blockIdx.y;
    const size_t base = (size_t)bh * T_ * DK_;

    {
        const float4* src = (const float4*)(Q + base + (size_t)qi * 64 * 64);
        #pragma unroll
        for (int i = 0; i < 4; i++) {
            int f = i * 256 + tid;
            float4 v = src[f];
            int r = f >> 4, c = (f & 15) << 2;
            float* qp = Qs + r * 64 + c;
            qp[0] = v.x * 0.125f; qp[1] = v.y * 0.125f;
            qp[2] = v.z * 0.125f; qp[3] = v.w * 0.125f;
        }
    }

    float m_i[8], l_i[8], o0[8], o1[8];
    #pragma unroll
    for (int r = 0; r < 8; r++) { m_i[r] = -1e30f; l_i[r] = 0.f; o0[r] = 0.f; o1[r] = 0.f; }

    __syncthreads();

    for (int kt = 0; kt <= qi; kt++) {
        const float4* ksrc = (const float4*)(K + base + (size_t)kt * 64 * 64);
        const float4* vsrc = (const float4*)(V + base + (size_t)kt * 64 * 64);
        #pragma unroll
        for (int i = 0; i < 4; i++) {
            int f = i * 256 + tid;
            int r = f >> 4, c = (f & 15) << 2;
            float4 kv = ksrc[f];
            float* kp = Ks + r * KV_PAD + c;
            kp[0] = kv.x; kp[1] = kv.y; kp[2] = kv.z; kp[3] = kv.w;
            float4 vv = vsrc[f];
            float* vp = Vs + r * KV_PAD + c;
            vp[0] = vv.x; vp[1] = vv.y; vp[2] = vv.z; vp[3] = vv.w;
        }
        __syncthreads();

        const bool diag = (kt == qi);

        #pragma unroll 1
        for (int r = 0; r < 8; r++) {
            const int i = w * 8 + r;
            float s0 = 0.f, s1 = 0.f;
            const float4* qrow = (const float4*)(Qs + i * 64);
            const float4* k0p  = (const float4*)(Ks + lane * KV_PAD);
            const float4* k1p  = (const float4*)(Ks + (lane + 32) * KV_PAD);
            #pragma unroll
            for (int d4 = 0; d4 < 16; d4++) {
                float4 qv = qrow[d4];
                float4 a = k0p[d4];
                float4 b = k1p[d4];
                s0 += qv.x * a.x + qv.y * a.y + qv.z * a.z + qv.w * a.w;
                s1 += qv.x * b.x + qv.y * b.y + qv.z * b.z + qv.w * b.w;
            }
            if (diag) {
                if (lane      > i) s0 = -1e30f;
                if (lane + 32 > i) s1 = -1e30f;
            }
            float mloc = fmaxf(s0, s1);
            #pragma unroll
            for (int off = 16; off > 0; off >>= 1)
                mloc = fmaxf(mloc, __shfl_xor_sync(0xffffffffu, mloc, off));
            float mnew = fmaxf(m_i[r], mloc);
            float p0 = __expf(s0 - mnew);
            float p1 = __expf(s1 - mnew);
            float rs = p0 + p1;
            #pragma unroll
            for (int off = 16; off > 0; off >>= 1)
                rs += __shfl_xor_sync(0xffffffffu, rs, off);
            float corr = __expf(m_i[r] - mnew);
            l_i[r] = l_i[r] * corr + rs;
            o0[r] *= corr;
            o1[r] *= corr;
            m_i[r] = mnew;
            Ps[i * 64 + lane]      = p0;
            Ps[i * 64 + lane + 32] = p1;
        }
        __syncwarp();

        #pragma unroll 1
        for (int jc = 0; jc < 64; jc += 4) {
            float v0[4], v1[4];
            #pragma unroll
            for (int jj = 0; jj < 4; jj++) {
                v0[jj] = Vs[(jc + jj) * KV_PAD + lane];
                v1[jj] = Vs[(jc + jj) * KV_PAD + lane + 32];
            }
            #pragma unroll
            for (int r = 0; r < 8; r++) {
                const int i = w * 8 + r;
                float4 p = *(const float4*)(Ps + i * 64 + jc);
                o0[r] += p.x * v0[0] + p.y * v0[1] + p.z * v0[2] + p.w * v0[3];
                o1[r] += p.x * v1[0] + p.y * v1[1] + p.z * v1[2] + p.w * v1[3];
            }
        }
        __syncthreads();
    }

    const int b = bh >> 4, h = bh & 15;
    #pragma unroll
    for (int r = 0; r < 8; r++) {
        int i = w * 8 + r;
        int t = qi * 64 + i;
        float inv = 1.0f / l_i[r];
        float* dst = att + ((size_t)(b * T_ + t)) * DM_ + h * DK_;
        dst[lane]      = o0[r] * inv;
        dst[lane + 32] = o1[r] * inv;
    }
}

// ---------------------------------------------------------------------------
extern "C" void kernel_launch(void* const* d_in, const int* in_sizes, int n_in,
                              void* d_out, int out_size)
{
    const float* x   = (const float*)d_in[0];
    const float* Wq  = (const float*)d_in[2];
    const float* Wqb = (const float*)d_in[3];
    const float* Wk  = (const float*)d_in[4];
    const float* Wkb = (const float*)d_in[5];
    const float* Wv  = (const float*)d_in[6];
    const float* Wvb = (const float*)d_in[7];
    const float* Wo  = (const float*)d_in[8];
    const float* Wob = (const float*)d_in[9];
    float* out = (float*)d_out;

    __nv_bfloat16 *xhi, *xlo, *whi, *wlo, *ahi, *alo;
    float *Qp, *Kp, *Vp, *Ap;
    cudaGetSymbolAddress((void**)&xhi, g_xhi);
    cudaGetSymbolAddress((void**)&xlo, g_xlo);
    cudaGetSymbolAddress((void**)&whi, g_whi);
    cudaGetSymbolAddress((void**)&wlo, g_wlo);
    cudaGetSymbolAddress((void**)&ahi, g_ahi);
    cudaGetSymbolAddress((void**)&alo, g_alo);
    cudaGetSymbolAddress((void**)&Qp, g_Q);
    cudaGetSymbolAddress((void**)&Kp, g_K);
    cudaGetSymbolAddress((void**)&Vp, g_V);
    cudaGetSymbolAddress((void**)&Ap, g_att);

    const int gemm_smem = 2 * STAGE_BYTES;  // 81920
    cudaFuncSetAttribute(gemm_tc_kernel, cudaFuncAttributeMaxDynamicSharedMemorySize, gemm_smem);
    const int attn_smem = (64 * 64 + 2 * 64 * KV_PAD + 64 * 64) * (int)sizeof(float);
    cudaFuncSetAttribute(attn_kernel, cudaFuncAttributeMaxDynamicSharedMemorySize, attn_smem);

    const int nx4 = M_ * DM_ / 4, nw4 = DM_ * DM_ / 4;
    split_bf16_kernel<<<nx4 / 256, 256>>>(x, xhi, xlo, nx4);
    split_bf16_kernel<<<nw4 / 256, 256>>>(Wq, whi + 0 * DM_ * DM_, wlo + 0 * DM_ * DM_, nw4);
    split_bf16_kernel<<<nw4 / 256, 256>>>(Wk, whi + 1 * DM_ * DM_, wlo + 1 * DM_ * DM_, nw4);
    split_bf16_kernel<<<nw4 / 256, 256>>>(Wv, whi + 2 * DM_ * DM_, wlo + 2 * DM_ * DM_, nw4);
    split_bf16_kernel<<<nw4 / 256, 256>>>(Wo, whi + 3 * DM_ * DM_, wlo + 3 * DM_ * DM_, nw4);

    dim3 ggrid(DM_ / 128, M_ / 128);   // (8, 64)
    gemm_tc_kernel<<<ggrid, 256, gemm_smem>>>(xhi, xlo, whi + 0 * DM_ * DM_, wlo + 0 * DM_ * DM_, Wqb, Qp, 0);
    gemm_tc_kernel<<<ggrid, 256, gemm_smem>>>(xhi, xlo, whi + 1 * DM_ * DM_, wlo + 1 * DM_ * DM_, Wkb, Kp, 0);
    gemm_tc_kernel<<<ggrid, 256, gemm_smem>>>(xhi, xlo, whi + 2 * DM_ * DM_, wlo + 2 * DM_ * DM_, Wvb, Vp, 0);

    attn_kernel<<<dim3(T_ / 64, B_ * H_), 256, attn_smem>>>(Qp, Kp, Vp, Ap);

    split_bf16_kernel<<<nx4 / 256, 256>>>(Ap, ahi, alo, nx4);
    gemm_tc_kernel<<<ggrid, 256, gemm_smem>>>(ahi, alo, whi + 3 * DM_ * DM_, wlo + 3 * DM_ * DM_, Wob, out, 1);
}

// round 6
// speedup vs baseline: 3.8020x; 2.4558x over previous
#include <cuda_runtime.h>
#include <cuda_bf16.h>
#include <cstdint>

#define B_  4
#define H_  16
#define T_  2048
#define DK_ 64
#define DM_ 1024
#define M_  (B_*T_)     // 8192

// ---------------- scratch (device globals; no allocations allowed) ----------
__device__ __nv_bfloat16 g_xhi[M_*DM_];
__device__ __nv_bfloat16 g_xlo[M_*DM_];
__device__ __nv_bfloat16 g_whi[4*DM_*DM_];
__device__ __nv_bfloat16 g_wlo[4*DM_*DM_];
__device__ __nv_bfloat16 g_qhi[M_*DM_];   // [b,h,t,d]
__device__ __nv_bfloat16 g_qlo[M_*DM_];
__device__ __nv_bfloat16 g_khi[M_*DM_];   // [b,h,t,d]
__device__ __nv_bfloat16 g_klo[M_*DM_];
__device__ __nv_bfloat16 g_vhi[M_*DM_];   // [b,h,d,t]  (transposed!)
__device__ __nv_bfloat16 g_vlo[M_*DM_];
__device__ __nv_bfloat16 g_ahi[M_*DM_];   // [b,t, h*64+d]
__device__ __nv_bfloat16 g_alo[M_*DM_];

// ---------------- portable PTX helpers (family-safe) -------------------------
__device__ __forceinline__ uint32_t smem_u32(const void* p) {
    uint32_t a;
    asm("{ .reg .u64 t; cvta.to.shared.u64 t, %1; cvt.u32.u64 %0, t; }" : "=r"(a) : "l"(p));
    return a;
}
__device__ __forceinline__ void cp_async16(uint32_t saddr, const void* gaddr) {
    asm volatile("cp.async.cg.shared.global [%0], [%1], 16;" :: "r"(saddr), "l"(gaddr));
}
#define CP_COMMIT() asm volatile("cp.async.commit_group;" ::: "memory")
#define CP_WAIT(n)  asm volatile("cp.async.wait_group %0;" :: "n"(n) : "memory")

__device__ __forceinline__ void ldsm_x4(uint32_t addr, uint32_t& r0, uint32_t& r1,
                                        uint32_t& r2, uint32_t& r3) {
    asm volatile("ldmatrix.sync.aligned.m8n8.x4.shared.b16 {%0,%1,%2,%3}, [%4];"
                 : "=r"(r0), "=r"(r1), "=r"(r2), "=r"(r3) : "r"(addr));
}
__device__ __forceinline__ void mma_bf16(float* c, const uint32_t* a, const uint32_t* b) {
    asm volatile(
        "mma.sync.aligned.m16n8k16.row.col.f32.bf16.bf16.f32 "
        "{%0,%1,%2,%3}, {%4,%5,%6,%7}, {%8,%9}, {%0,%1,%2,%3};"
        : "+f"(c[0]), "+f"(c[1]), "+f"(c[2]), "+f"(c[3])
        : "r"(a[0]), "r"(a[1]), "r"(a[2]), "r"(a[3]), "r"(b[0]), "r"(b[1]));
}

// pack two floats into hi/lo bf16x2 (element 0 in low 16 bits)
__device__ __forceinline__ void split2(float x0, float x1, uint32_t& hi, uint32_t& lo) {
    __nv_bfloat16 h0 = __float2bfloat16(x0), h1 = __float2bfloat16(x1);
    uint32_t u0 = *(uint16_t*)&h0, u1 = *(uint16_t*)&h1;
    hi = u0 | (u1 << 16);
    float r0 = x0 - __bfloat162float(h0), r1 = x1 - __bfloat162float(h1);
    __nv_bfloat16 g0 = __float2bfloat16(r0), g1 = __float2bfloat16(r1);
    uint32_t v0 = *(uint16_t*)&g0, v1 = *(uint16_t*)&g1;
    lo = v0 | (v1 << 16);
}
__device__ __forceinline__ uint32_t pack_bf16(float x0, float x1) {
    __nv_bfloat16 h0 = __float2bfloat16(x0), h1 = __float2bfloat16(x1);
    uint32_t u0 = *(uint16_t*)&h0, u1 = *(uint16_t*)&h1;
    return u0 | (u1 << 16);
}

// ---------------- fp32 -> bf16 hi/lo split -----------------------------------
__global__ __launch_bounds__(256) void split_bf16_kernel(
    const float* __restrict__ x, __nv_bfloat16* __restrict__ hi,
    __nv_bfloat16* __restrict__ lo, int n4)
{
    int i = blockIdx.x * blockDim.x + threadIdx.x;
    if (i >= n4) return;
    float4 v = ((const float4*)x)[i];
    float f[4] = {v.x, v.y, v.z, v.w};
    union { __nv_bfloat16 b[4]; uint2 u; } Hh, Ll;
    #pragma unroll
    for (int k = 0; k < 4; k++) {
        Hh.b[k] = __float2bfloat16(f[k]);
        Ll.b[k] = __float2bfloat16(f[k] - __bfloat162float(Hh.b[k]));
    }
    ((uint2*)hi)[i] = Hh.u;
    ((uint2*)lo)[i] = Ll.u;
}

// ---------------- mma.sync split-bf16 GEMM: C = A @ W^T + bias ---------------
// modes: 0 = bf16 hi/lo split-head [b,h,t,d]; 2 = bf16 hi/lo transposed
// [b,h,d,t]; 1 = fp32 row-major.
#define PITCH 40
#define TILE_BYTES (128 * PITCH * 2)      // 10240
#define STAGE_BYTES (4 * TILE_BYTES)      // 40960

__device__ __forceinline__ void issue_stage(uint32_t sb, int stage,
    const __nv_bfloat16* __restrict__ Ahi, const __nv_bfloat16* __restrict__ Alo,
    const __nv_bfloat16* __restrict__ Whi, const __nv_bfloat16* __restrict__ Wlo,
    int m0, int n0, int k0, int tid)
{
    const uint32_t base = sb + stage * STAGE_BYTES;
    const __nv_bfloat16* srcs[4] = {Ahi, Alo, Whi, Wlo};
    const int r0s[4] = {m0, m0, n0, n0};
    #pragma unroll
    for (int t = 0; t < 4; t++) {
        #pragma unroll
        for (int it = 0; it < 2; it++) {
            int idx = it * 256 + tid;          // 0..511
            int r = idx >> 2, c4 = idx & 3;
            cp_async16(base + t * TILE_BYTES + r * (PITCH * 2) + c4 * 16,
                       srcs[t] + (size_t)(r0s[t] + r) * 1024 + k0 + c4 * 8);
        }
    }
}

__global__ __launch_bounds__(256) void gemm_tc_kernel(
    const __nv_bfloat16* __restrict__ Ahi, const __nv_bfloat16* __restrict__ Alo,
    const __nv_bfloat16* __restrict__ Whi, const __nv_bfloat16* __restrict__ Wlo,
    const float* __restrict__ bias,
    __nv_bfloat16* __restrict__ Chi, __nv_bfloat16* __restrict__ Clo,
    float* __restrict__ Cf, int mode)
{
    extern __shared__ char smem[];
    const uint32_t sb = smem_u32(smem);
    const int tid = threadIdx.x;
    const int wid = tid >> 5, lane = tid & 31;
    const int m0 = blockIdx.y * 128, n0 = blockIdx.x * 128;
    const int wm = (wid & 3) * 32;
    const int wn = (wid >> 2) * 64;
    const int rl = lane & 7, q = lane >> 3;

    float acc[2][8][4];
    #pragma unroll
    for (int mt = 0; mt < 2; mt++)
        #pragma unroll
        for (int nt = 0; nt < 8; nt++)
            #pragma unroll
            for (int e = 0; e < 4; e++) acc[mt][nt][e] = 0.f;

    issue_stage(sb, 0, Ahi, Alo, Whi, Wlo, m0, n0, 0, tid);
    CP_COMMIT();

    const uint32_t a_row = rl + (q & 1) * 8;
    const uint32_t a_cofs = (q >> 1) * 8;
    const uint32_t b_row = rl + (q >> 1) * 8;
    const uint32_t b_cofs = (q & 1) * 8;

    for (int s = 0; s < 32; s++) {
        if (s < 31) {
            issue_stage(sb, (s + 1) & 1, Ahi, Alo, Whi, Wlo, m0, n0, (s + 1) * 32, tid);
            CP_COMMIT();
            CP_WAIT(1);
        } else {
            CP_WAIT(0);
        }
        __syncthreads();

        const uint32_t st = sb + (s & 1) * STAGE_BYTES;
        #pragma unroll
        for (int k16 = 0; k16 < 32; k16 += 16) {
            uint32_t ah[2][4], al[2][4];
            #pragma unroll
            for (int mt = 0; mt < 2; mt++) {
                uint32_t ro = (wm + mt * 16 + a_row) * (PITCH * 2) + (k16 + a_cofs) * 2;
                ldsm_x4(st + 0 * TILE_BYTES + ro, ah[mt][0], ah[mt][1], ah[mt][2], ah[mt][3]);
                ldsm_x4(st + 1 * TILE_BYTES + ro, al[mt][0], al[mt][1], al[mt][2], al[mt][3]);
            }
            uint32_t bh[8][2], bl[8][2];
            #pragma unroll
            for (int np = 0; np < 4; np++) {
                uint32_t ro = (wn + np * 16 + b_row) * (PITCH * 2) + (k16 + b_cofs) * 2;
                ldsm_x4(st + 2 * TILE_BYTES + ro,
                        bh[np*2][0], bh[np*2][1], bh[np*2+1][0], bh[np*2+1][1]);
                ldsm_x4(st + 3 * TILE_BYTES + ro,
                        bl[np*2][0], bl[np*2][1], bl[np*2+1][0], bl[np*2+1][1]);
            }
            #pragma unroll
            for (int mt = 0; mt < 2; mt++)
                #pragma unroll
                for (int nt = 0; nt < 8; nt++) {
                    mma_bf16(acc[mt][nt], ah[mt], bh[nt]);
                    mma_bf16(acc[mt][nt], ah[mt], bl[nt]);
                    mma_bf16(acc[mt][nt], al[mt], bh[nt]);
                }
        }
        __syncthreads();
    }

    // Epilogue
    const int g = lane >> 2, tq = lane & 3;
    #pragma unroll
    for (int mt = 0; mt < 2; mt++) {
        #pragma unroll
        for (int half = 0; half < 2; half++) {
            int m = m0 + wm + mt * 16 + g + half * 8;
            int b = m >> 11, t = m & 2047;
            #pragma unroll
            for (int nt = 0; nt < 8; nt++) {
                int n = n0 + wn + nt * 8 + 2 * tq;
                float vx = acc[mt][nt][half * 2 + 0] + __ldg(bias + n);
                float vy = acc[mt][nt][half * 2 + 1] + __ldg(bias + n + 1);
                int h = n >> 6, d = n & 63;
                if (mode == 0) {
                    size_t off = (((size_t)(b * 16 + h)) * 2048 + t) * 64 + d;
                    uint32_t hi, lo;
                    split2(vx, vy, hi, lo);
                    *(uint32_t*)(Chi + off) = hi;
                    *(uint32_t*)(Clo + off) = lo;
                } else if (mode == 2) {
                    // transposed: [b,h,d,t]
                    size_t off = (((size_t)(b * 16 + h)) * 64 + d) * 2048 + t;
                    __nv_bfloat16 h0 = __float2bfloat16(vx);
                    __nv_bfloat16 h1 = __float2bfloat16(vy);
                    Chi[off] = h0;
                    Chi[off + 2048] = h1;
                    Clo[off]        = __float2bfloat16(vx - __bfloat162float(h0));
                    Clo[off + 2048] = __float2bfloat16(vy - __bfloat162float(h1));
                } else {
                    float2 v = make_float2(vx, vy);
                    *(float2*)(Cf + (size_t)m * 1024 + n) = v;
                }
            }
        }
    }
}

// ---------------- tensor-core flash attention (causal) -----------------------
// grid (T/64, B*H), 128 threads = 4 warps; warp w owns Q rows w*16..w*16+15.
// K tiles [t][d] from [b,h,t,d]; V tiles [d][t] from [b,h,d,t] (transposed).
#define AP 72                              // smem pitch in bf16 (144B rows)
#define ATILE (64 * AP * 2)                // 9216 B per 64x64 tile
#define AQ_OFF 0
#define AST_OFF (2 * ATILE)                // stages start after Qhi,Qlo
#define ASTAGE (4 * ATILE)                 // khi,klo,vhi,vlo
#define ATTN_SMEM (AST_OFF + 2 * ASTAGE)   // 92160

__device__ __forceinline__ void attn_load_tile(uint32_t sbase,
    const __nv_bfloat16* __restrict__ gsrc, int rowstride, int tid)
{
    #pragma unroll
    for (int it = 0; it < 4; it++) {
        int idx = it * 128 + tid;          // 0..511
        int r = idx >> 3, c = idx & 7;
        cp_async16(sbase + r * (AP * 2) + c * 16,
                   gsrc + (size_t)r * rowstride + c * 8);
    }
}

__global__ __launch_bounds__(128) void attn_tc_kernel(
    const __nv_bfloat16* __restrict__ Qhi, const __nv_bfloat16* __restrict__ Qlo,
    const __nv_bfloat16* __restrict__ Khi, const __nv_bfloat16* __restrict__ Klo,
    const __nv_bfloat16* __restrict__ VThi, const __nv_bfloat16* __restrict__ VTlo,
    __nv_bfloat16* __restrict__ Ahi, __nv_bfloat16* __restrict__ Alo)
{
    extern __shared__ char smem[];
    const uint32_t sb = smem_u32(smem);
    const int tid = threadIdx.x;
    const int w = tid >> 5, lane = tid & 31;
    const int qi = blockIdx.x, bh = blockIdx.y;
    const size_t baseTD = (size_t)bh * T_ * 64;   // [t][d] layouts
    const int rl = lane & 7, q = lane >> 3;
    const int g = lane >> 2, tq = lane & 3;

    // ---- prologue loads: Q tile + kv tile 0
    attn_load_tile(sb + AQ_OFF,        Qhi + baseTD + (size_t)qi * 64 * 64, 64, tid);
    attn_load_tile(sb + AQ_OFF + ATILE,Qlo + baseTD + (size_t)qi * 64 * 64, 64, tid);
    CP_COMMIT();
    {
        uint32_t st0 = sb + AST_OFF;
        attn_load_tile(st0 + 0*ATILE, Khi + baseTD, 64, tid);
        attn_load_tile(st0 + 1*ATILE, Klo + baseTD, 64, tid);
        attn_load_tile(st0 + 2*ATILE, VThi + baseTD, 2048, tid);
        attn_load_tile(st0 + 3*ATILE, VTlo + baseTD, 2048, tid);
        CP_COMMIT();
    }

    CP_WAIT(1);
    __syncthreads();

    // ---- Q fragments (persist in registers)
    const uint32_t a_row = rl + (q & 1) * 8, a_cofs = (q >> 1) * 8;
    const uint32_t b_row = rl + (q >> 1) * 8, b_cofs = (q & 1) * 8;
    uint32_t qh[4][4], ql[4][4];
    #pragma unroll
    for (int kk = 0; kk < 4; kk++) {
        uint32_t ro = (w * 16 + a_row) * (AP * 2) + (kk * 16 + a_cofs) * 2;
        ldsm_x4(sb + AQ_OFF + ro,         qh[kk][0], qh[kk][1], qh[kk][2], qh[kk][3]);
        ldsm_x4(sb + AQ_OFF + ATILE + ro, ql[kk][0], ql[kk][1], ql[kk][2], ql[kk][3]);
    }

    float oacc[8][4];
    #pragma unroll
    for (int nt = 0; nt < 8; nt++)
        #pragma unroll
        for (int e = 0; e < 4; e++) oacc[nt][e] = 0.f;
    float m_r[2] = {-1e30f, -1e30f}, l_r[2] = {0.f, 0.f};

    for (int kt = 0; kt <= qi; kt++) {
        const uint32_t st = sb + AST_OFF + (kt & 1) * ASTAGE;
        if (kt < qi) {
            uint32_t ns = sb + AST_OFF + ((kt + 1) & 1) * ASTAGE;
            const size_t offT = baseTD + (size_t)(kt + 1) * 64 * 64;  // K rows
            const size_t offV = baseTD + (size_t)(kt + 1) * 64;       // VT cols
            attn_load_tile(ns + 0*ATILE, Khi + offT, 64, tid);
            attn_load_tile(ns + 1*ATILE, Klo + offT, 64, tid);
            attn_load_tile(ns + 2*ATILE, VThi + offV, 2048, tid);
            attn_load_tile(ns + 3*ATILE, VTlo + offV, 2048, tid);
            CP_COMMIT();
            CP_WAIT(1);
        } else {
            CP_WAIT(0);
        }
        __syncthreads();

        // ---- S = Q K^T (3-term split)
        float sacc[8][4];
        #pragma unroll
        for (int nt = 0; nt < 8; nt++)
            #pragma unroll
            for (int e = 0; e < 4; e++) sacc[nt][e] = 0.f;

        #pragma unroll
        for (int kk = 0; kk < 4; kk++) {
            uint32_t kh[8][2], kl[8][2];
            #pragma unroll
            for (int np = 0; np < 4; np++) {
                uint32_t ro = (np * 16 + b_row) * (AP * 2) + (kk * 16 + b_cofs) * 2;
                ldsm_x4(st + 0*ATILE + ro,
                        kh[np*2][0], kh[np*2][1], kh[np*2+1][0], kh[np*2+1][1]);
                ldsm_x4(st + 1*ATILE + ro,
                        kl[np*2][0], kl[np*2][1], kl[np*2+1][0], kl[np*2+1][1]);
            }
            #pragma unroll
            for (int nt = 0; nt < 8; nt++) {
                mma_bf16(sacc[nt], qh[kk], kh[nt]);
                mma_bf16(sacc[nt], qh[kk], kl[nt]);
                mma_bf16(sacc[nt], ql[kk], kh[nt]);
            }
        }

        // ---- scale + causal mask
        const bool diag = (kt == qi);
        #pragma unroll
        for (int nt = 0; nt < 8; nt++) {
            #pragma unroll
            for (int e = 0; e < 4; e++) {
                float s = sacc[nt][e] * 0.125f;
                if (diag) {
                    int row = w * 16 + g + (e >> 1) * 8;
                    int col = nt * 8 + 2 * tq + (e & 1);
                    if (col > row) s = -1e30f;
                }
                sacc[nt][e] = s;
            }
        }

        // ---- online softmax (per thread: rows g, g+8)
        #pragma unroll
        for (int r = 0; r < 2; r++) {
            float mloc = -1e30f;
            #pragma unroll
            for (int nt = 0; nt < 8; nt++)
                mloc = fmaxf(mloc, fmaxf(sacc[nt][r*2], sacc[nt][r*2+1]));
            mloc = fmaxf(mloc, __shfl_xor_sync(0xffffffffu, mloc, 1));
            mloc = fmaxf(mloc, __shfl_xor_sync(0xffffffffu, mloc, 2));
            float mnew = fmaxf(m_r[r], mloc);
            float rs = 0.f;
            #pragma unroll
            for (int nt = 0; nt < 8; nt++) {
                float p0 = __expf(sacc[nt][r*2]   - mnew);
                float p1 = __expf(sacc[nt][r*2+1] - mnew);
                sacc[nt][r*2] = p0; sacc[nt][r*2+1] = p1;
                rs += p0 + p1;
            }
            rs += __shfl_xor_sync(0xffffffffu, rs, 1);
            rs += __shfl_xor_sync(0xffffffffu, rs, 2);
            float corr = __expf(m_r[r] - mnew);
            l_r[r] = l_r[r] * corr + rs;
            m_r[r] = mnew;
            #pragma unroll
            for (int nt = 0; nt < 8; nt++) {
                oacc[nt][r*2]   *= corr;
                oacc[nt][r*2+1] *= corr;
            }
        }

        // ---- O += P V  (P hi/lo from registers, V^T tiles like K)
        #pragma unroll
        for (int j = 0; j < 4; j++) {
            uint32_t pah[4], pal[4];
            split2(sacc[2*j][0],   sacc[2*j][1],   pah[0], pal[0]);
            split2(sacc[2*j][2],   sacc[2*j][3],   pah[1], pal[1]);
            split2(sacc[2*j+1][0], sacc[2*j+1][1], pah[2], pal[2]);
            split2(sacc[2*j+1][2], sacc[2*j+1][3], pah[3], pal[3]);

            uint32_t vh[8][2], vl[8][2];
            #pragma unroll
            for (int np = 0; np < 4; np++) {
                uint32_t ro = (np * 16 + b_row) * (AP * 2) + (j * 16 + b_cofs) * 2;
                ldsm_x4(st + 2*ATILE + ro,
                        vh[np*2][0], vh[np*2][1], vh[np*2+1][0], vh[np*2+1][1]);
                ldsm_x4(st + 3*ATILE + ro,
                        vl[np*2][0], vl[np*2][1], vl[np*2+1][0], vl[np*2+1][1]);
            }
            #pragma unroll
            for (int nt = 0; nt < 8; nt++) {
                mma_bf16(oacc[nt], pah, vh[nt]);
                mma_bf16(oacc[nt], pah, vl[nt]);
                mma_bf16(oacc[nt], pal, vh[nt]);
            }
        }
        __syncthreads();
    }

    // ---- epilogue: normalize, split hi/lo, write [b,t,h*64+d]
    const int b = bh >> 4, h = bh & 15;
    #pragma unroll
    for (int r = 0; r < 2; r++) {
        float inv = 1.0f / l_r[r];
        int t = qi * 64 + w * 16 + g + r * 8;
        size_t rowo = ((size_t)(b * T_ + t)) * DM_ + h * 64;
        #pragma unroll
        for (int nt = 0; nt < 8; nt++) {
            int d = nt * 8 + 2 * tq;
            uint32_t hi, lo;
            split2(oacc[nt][r*2] * inv, oacc[nt][r*2+1] * inv, hi, lo);
            *(uint32_t*)(Ahi + rowo + d) = hi;
            *(uint32_t*)(Alo + rowo + d) = lo;
        }
    }
}

// ---------------------------------------------------------------------------
extern "C" void kernel_launch(void* const* d_in, const int* in_sizes, int n_in,
                              void* d_out, int out_size)
{
    const float* x   = (const float*)d_in[0];
    const float* Wq  = (const float*)d_in[2];
    const float* Wqb = (const float*)d_in[3];
    const float* Wk  = (const float*)d_in[4];
    const float* Wkb = (const float*)d_in[5];
    const float* Wv  = (const float*)d_in[6];
    const float* Wvb = (const float*)d_in[7];
    const float* Wo  = (const float*)d_in[8];
    const float* Wob = (const float*)d_in[9];
    float* out = (float*)d_out;

    __nv_bfloat16 *xhi, *xlo, *whi, *wlo;
    __nv_bfloat16 *qhi, *qlo, *khi, *klo, *vhi, *vlo, *ahi, *alo;
    cudaGetSymbolAddress((void**)&xhi, g_xhi);
    cudaGetSymbolAddress((void**)&xlo, g_xlo);
    cudaGetSymbolAddress((void**)&whi, g_whi);
    cudaGetSymbolAddress((void**)&wlo, g_wlo);
    cudaGetSymbolAddress((void**)&qhi, g_qhi);
    cudaGetSymbolAddress((void**)&qlo, g_qlo);
    cudaGetSymbolAddress((void**)&khi, g_khi);
    cudaGetSymbolAddress((void**)&klo, g_klo);
    cudaGetSymbolAddress((void**)&vhi, g_vhi);
    cudaGetSymbolAddress((void**)&vlo, g_vlo);
    cudaGetSymbolAddress((void**)&ahi, g_ahi);
    cudaGetSymbolAddress((void**)&alo, g_alo);

    const int gemm_smem = 2 * STAGE_BYTES;  // 81920
    cudaFuncSetAttribute(gemm_tc_kernel, cudaFuncAttributeMaxDynamicSharedMemorySize, gemm_smem);
    cudaFuncSetAttribute(attn_tc_kernel, cudaFuncAttributeMaxDynamicSharedMemorySize, ATTN_SMEM);

    const int nx4 = M_ * DM_ / 4, nw4 = DM_ * DM_ / 4;
    split_bf16_kernel<<<nx4 / 256, 256>>>(x, xhi, xlo, nx4);
    split_bf16_kernel<<<nw4 / 256, 256>>>(Wq, whi + 0 * DM_ * DM_, wlo + 0 * DM_ * DM_, nw4);
    split_bf16_kernel<<<nw4 / 256, 256>>>(Wk, whi + 1 * DM_ * DM_, wlo + 1 * DM_ * DM_, nw4);
    split_bf16_kernel<<<nw4 / 256, 256>>>(Wv, whi + 2 * DM_ * DM_, wlo + 2 * DM_ * DM_, nw4);
    split_bf16_kernel<<<nw4 / 256, 256>>>(Wo, whi + 3 * DM_ * DM_, wlo + 3 * DM_ * DM_, nw4);

    dim3 ggrid(DM_ / 128, M_ / 128);   // (8, 64)
    gemm_tc_kernel<<<ggrid, 256, gemm_smem>>>(xhi, xlo, whi + 0 * DM_ * DM_, wlo + 0 * DM_ * DM_,
                                              Wqb, qhi, qlo, nullptr, 0);
    gemm_tc_kernel<<<ggrid, 256, gemm_smem>>>(xhi, xlo, whi + 1 * DM_ * DM_, wlo + 1 * DM_ * DM_,
                                              Wkb, khi, klo, nullptr, 0);
    gemm_tc_kernel<<<ggrid, 256, gemm_smem>>>(xhi, xlo, whi + 2 * DM_ * DM_, wlo + 2 * DM_ * DM_,
                                              Wvb, vhi, vlo, nullptr, 2);

    attn_tc_kernel<<<dim3(T_ / 64, B_ * H_), 128, ATTN_SMEM>>>(
        qhi, qlo, khi, klo, vhi, vlo, ahi, alo);

    gemm_tc_kernel<<<ggrid, 256, gemm_smem>>>(ahi, alo, whi + 3 * DM_ * DM_, wlo + 3 * DM_ * DM_,
                                              Wob, nullptr, nullptr, out, 1);
}